// round 3
// baseline (speedup 1.0000x reference)
#include <cuda_runtime.h>
#include <cstdint>

#define B_  64
#define OH_ 120
#define OW_ 160
#define HW_ (OH_ * OW_)          // 19200
#define TOTAL_ (B_ * HW_)        // 1,228,800
#define IN_H_ 480.0f
#define IN_W_ 640.0f
#define THRESH_ 0.5f

#define NT 128                   // threads per block
#define PPT 4                    // pixels per thread (vectorized)
#define PPB (NT * PPT)           // 512 pixels per block

__global__ __launch_bounds__(NT)
void centerface_decode_kernel(const float* __restrict__ heatmap,   // [B,1,OH,OW]
                              const float* __restrict__ scale,     // [B,2,OH,OW]
                              const float* __restrict__ offset,    // [B,2,OH,OW]
                              const float* __restrict__ landmark,  // [B,10,OH,OW]
                              float* __restrict__ boxes,           // [B,HW,5]
                              float* __restrict__ lms,             // [B,HW,10]
                              float* __restrict__ keep)            // [B,HW]
{
    __shared__ float box_s[PPB * 5];     // 10 KB
    __shared__ float lm_s [PPB * 10];    // 20 KB

    const int tid  = threadIdx.x;
    const int base = blockIdx.x * PPB;           // first pixel of block
    const int idx0 = base + tid * PPT;           // first pixel of this thread

    // 4 consecutive pixels: same batch (HW_%4==0) and same row (OW_%4==0).
    const int b  = idx0 / HW_;
    const int p0 = idx0 - b * HW_;
    const int y  = p0 / OW_;
    const float yf = (float)y;

    // ---- vector loads (LDG.128) ----
    union F4 { float4 v; float a[4]; };
    F4 hm, sc0, sc1, o0;
    hm.v  = *(const float4*)(heatmap + idx0);
    const float* scp = scale + (size_t)b * (2 * HW_) + p0;
    sc0.v = *(const float4*)(scp);
    sc1.v = *(const float4*)(scp + HW_);
    o0.v  = *(const float4*)(offset + (size_t)b * (2 * HW_) + p0);

    F4 lm[10];
    const float* lmp = landmark + (size_t)b * (10 * HW_) + p0;
#pragma unroll
    for (int j = 0; j < 10; j++)
        lm[j].v = *(const float4*)(lmp + (size_t)j * HW_);

    // ---- per-pixel compute + SMEM staging ----
    F4 kp;
    float* bs = box_s + tid * (5 * PPT);         // 20 floats, contiguous
    float* ls = lm_s  + tid * (10 * PPT);        // 40 floats, contiguous

#pragma unroll
    for (int q = 0; q < 4; q++) {
        float s0 = __expf(sc0.a[q]) * 4.0f;
        float s1 = __expf(sc1.a[q]) * 4.0f;

        float y1_raw = (yf + o0.a[q] + 0.5f) * 4.0f - s0 * 0.5f;
        float y1c = fmaxf(y1_raw, 0.0f);
        float y1  = fminf(y1c, IN_H_);
        float x1  = fminf(y1c, IN_W_);
        float y2  = fminf(y1 + s0, IN_H_);
        float x2  = fminf(x1 + s1, IN_W_);

        float h = hm.a[q];
        float m = (h >= THRESH_) ? 1.0f : 0.0f;
        kp.a[q] = m;

        float* bq = bs + q * 5;
        bq[0] = x1 * m;
        bq[1] = y1 * m;
        bq[2] = x2 * m;
        bq[3] = y2 * m;
        bq[4] = h  * m;

        float* lq = ls + q * 10;
#pragma unroll
        for (int j = 0; j < 10; j += 2) {
            lq[j]     = fmaf(lm[j].a[q],     s0, y1) * m;
            lq[j + 1] = fmaf(lm[j + 1].a[q], s1, x1) * m;
        }
    }

    // keep: 4 consecutive floats per thread -> STG.128, fully coalesced
    *(float4*)(keep + idx0) = kp.v;

    __syncthreads();

    // ---- cooperative coalesced flush (128-bit streaming stores) ----
    {
        const float4* src = (const float4*)box_s;     // 640 float4
        float4*       dst = (float4*)(boxes + (size_t)base * 5);
#pragma unroll
        for (int i = 0; i < 640 / NT; i++)
            __stcs(dst + i * NT + tid, src[i * NT + tid]);
    }
    {
        const float4* src = (const float4*)lm_s;      // 1280 float4
        float4*       dst = (float4*)(lms + (size_t)base * 10);
#pragma unroll
        for (int i = 0; i < 1280 / NT; i++)
            __stcs(dst + i * NT + tid, src[i * NT + tid]);
    }
}

extern "C" void kernel_launch(void* const* d_in, const int* in_sizes, int n_in,
                              void* d_out, int out_size)
{
    const float* heatmap  = (const float*)d_in[0];
    const float* scale    = (const float*)d_in[1];
    const float* offset   = (const float*)d_in[2];
    const float* landmark = (const float*)d_in[3];

    float* out   = (float*)d_out;
    float* boxes = out;                          // [B,HW,5]
    float* lms   = out + (size_t)TOTAL_ * 5;     // [B,HW,10]
    float* keep  = out + (size_t)TOTAL_ * 15;    // [B,HW]

    int blocks = TOTAL_ / PPB;                   // 2400
    centerface_decode_kernel<<<blocks, NT>>>(heatmap, scale, offset, landmark,
                                             boxes, lms, keep);
}

// round 4
// speedup vs baseline: 1.1813x; 1.1813x over previous
#include <cuda_runtime.h>
#include <cstdint>

#define B_  64
#define OH_ 120
#define OW_ 160
#define HW_ (OH_ * OW_)          // 19200
#define TOTAL_ (B_ * HW_)        // 1,228,800
#define IN_H_ 480.0f
#define IN_W_ 640.0f
#define THRESH_ 0.5f

#define NT  256                  // threads per block (8 warps)
#define PPT 2                    // pixels per thread
#define PPW 64                   // pixels per warp (32*PPT)
#define PPB (NT * PPT)           // 512 pixels per block

__global__ __launch_bounds__(NT, 6)
void centerface_decode_kernel(const float* __restrict__ heatmap,   // [B,1,OH,OW]
                              const float* __restrict__ scale,     // [B,2,OH,OW]
                              const float* __restrict__ offset,    // [B,2,OH,OW]
                              const float* __restrict__ landmark,  // [B,10,OH,OW]
                              float* __restrict__ boxes,           // [B,HW,5]
                              float* __restrict__ lms,             // [B,HW,10]
                              float* __restrict__ keep)            // [B,HW]
{
    __shared__ float box_s[8][PPW * 5];     // 8 * 1280B = 10 KB
    __shared__ float lm_s [8][PPW * 10];    // 8 * 2560B = 20 KB

    const int tid  = threadIdx.x;
    const int wid  = tid >> 5;
    const int lane = tid & 31;

    const int base     = blockIdx.x * PPB;
    const int warpbase = base + wid * PPW;           // first pixel of this warp
    const int idx0     = warpbase + lane * PPT;      // first pixel of this thread

    // 2 consecutive pixels: same batch (HW_%2==0) and same row (OW_%2==0).
    const int b  = idx0 / HW_;
    const int p0 = idx0 - b * HW_;
    const int y  = p0 / OW_;
    const float yf = (float)y;

    // ---- vector loads (LDG.64, fully coalesced) ----
    union F2 { float2 v; float a[2]; };
    F2 hm, sc0, sc1, o0;
    hm.v  = *(const float2*)(heatmap + idx0);
    const float* scp = scale + (size_t)b * (2 * HW_) + p0;
    sc0.v = *(const float2*)(scp);
    sc1.v = *(const float2*)(scp + HW_);
    o0.v  = *(const float2*)(offset + (size_t)b * (2 * HW_) + p0);

    F2 lm[10];
    const float* lmp = landmark + (size_t)b * (10 * HW_) + p0;
#pragma unroll
    for (int j = 0; j < 10; j++)
        lm[j].v = *(const float2*)(lmp + (size_t)j * HW_);

    // ---- per-pixel compute, stage into this warp's SMEM slice ----
    F2 kp;
    float* bs = box_s[wid] + lane * (5 * PPT);   // 10 contiguous floats
    float* ls = lm_s [wid] + lane * (10 * PPT);  // 20 contiguous floats

#pragma unroll
    for (int q = 0; q < PPT; q++) {
        float s0 = __expf(sc0.a[q]) * 4.0f;
        float s1 = __expf(sc1.a[q]) * 4.0f;

        float y1_raw = (yf + o0.a[q] + 0.5f) * 4.0f - s0 * 0.5f;
        float y1c = fmaxf(y1_raw, 0.0f);
        float y1  = fminf(y1c, IN_H_);
        float x1  = fminf(y1c, IN_W_);
        float y2  = fminf(y1 + s0, IN_H_);
        float x2  = fminf(x1 + s1, IN_W_);

        float h = hm.a[q];
        float m = (h >= THRESH_) ? 1.0f : 0.0f;
        kp.a[q] = m;

        float* bq = bs + q * 5;
        bq[0] = x1 * m;
        bq[1] = y1 * m;
        bq[2] = x2 * m;
        bq[3] = y2 * m;
        bq[4] = h  * m;

        float* lq = ls + q * 10;
#pragma unroll
        for (int j = 0; j < 10; j += 2) {
            lq[j]     = fmaf(lm[j].a[q],     s0, y1) * m;
            lq[j + 1] = fmaf(lm[j + 1].a[q], s1, x1) * m;
        }
    }

    // keep: 2 consecutive floats per thread -> STG.64, coalesced
    *(float2*)(keep + idx0) = kp.v;

    __syncwarp();   // warp-local: own warp's STS visible to own warp's LDS

    // ---- warp-local coalesced flush (128-bit streaming stores) ----
    {
        // boxes: 64 px * 5 = 320 floats = 80 float4 per warp
        const float4* src = (const float4*)box_s[wid];
        float4*       dst = (float4*)(boxes + (size_t)warpbase * 5);
        __stcs(dst + lane,      src[lane]);
        __stcs(dst + 32 + lane, src[32 + lane]);
        if (lane < 16) __stcs(dst + 64 + lane, src[64 + lane]);
    }
    {
        // landmarks: 64 px * 10 = 640 floats = 160 float4 per warp (5 full rounds)
        const float4* src = (const float4*)lm_s[wid];
        float4*       dst = (float4*)(lms + (size_t)warpbase * 10);
#pragma unroll
        for (int i = 0; i < 5; i++)
            __stcs(dst + i * 32 + lane, src[i * 32 + lane]);
    }
}

extern "C" void kernel_launch(void* const* d_in, const int* in_sizes, int n_in,
                              void* d_out, int out_size)
{
    const float* heatmap  = (const float*)d_in[0];
    const float* scale    = (const float*)d_in[1];
    const float* offset   = (const float*)d_in[2];
    const float* landmark = (const float*)d_in[3];

    float* out   = (float*)d_out;
    float* boxes = out;                          // [B,HW,5]
    float* lms   = out + (size_t)TOTAL_ * 5;     // [B,HW,10]
    float* keep  = out + (size_t)TOTAL_ * 15;    // [B,HW]

    int blocks = TOTAL_ / PPB;                   // 2400
    centerface_decode_kernel<<<blocks, NT>>>(heatmap, scale, offset, landmark,
                                             boxes, lms, keep);
}